// round 12
// baseline (speedup 1.0000x reference)
#include <cuda_runtime.h>
#include <cuda_fp16.h>
#include <math.h>
#include <stdint.h>

// Problem constants
#define BATCH   32
#define HDIM    64
#define WDIM    64
#define CDIM    256
#define WS      8
#define SS      4
#define HEADS   8
#define HD      32
#define WS2     64
#define NWPI    64
#define NWIN    2048
#define QKV_N   768
#define MROWS   (NWIN * WS2)          // 131072
#define SCALE   0.17677669529663687f

// Scratch (all fp16)
__device__ __half g_qkv_f16[(size_t)MROWS * QKV_N];
__device__ __half g_x_f16[(size_t)MROWS * CDIM];            // window-ordered
__device__ __half g_att_f16[(size_t)MROWS * CDIM];
__device__ __half g_wq[QKV_N * CDIM];                       // [n][k]
__device__ __half g_wo[CDIM * CDIM];
__device__ float g_bias[HEADS * 4 * WS2 * WS2];             // bias+mask per window class

// GEMM smem: 3 stages x {A 16K, B 16K}
#define STAGE_BYTES 32768
#define SOFF_B      16384
#define OFF_BIAS    98304
#define SMEM_GEMM   98816

// Attention smem: Q 8K | K 8K | V 8K  (Q/K reused for P)
#define SMEM_ATT    24576

__device__ __forceinline__ int global_row(int win, int m) {
    int b  = win >> 6;
    int wi = win & 63;
    int wy = wi >> 3, wx = wi & 7;
    int ty = m >> 3,  tx = m & 7;
    int sy = (wy * 8 + ty + SS) & 63;
    int sx = (wx * 8 + tx + SS) & 63;
    return b * (HDIM * WDIM) + sy * WDIM + sx;
}

__device__ __forceinline__ uint32_t smem_u32(const void* p) {
    uint32_t a;
    asm("{ .reg .u64 t; cvta.to.shared.u64 t, %1; cvt.u32.u64 %0, t; }" : "=r"(a) : "l"(p));
    return a;
}
__device__ __forceinline__ uint32_t sw128(uint32_t off) {
    return off ^ ((off >> 3) & 0x70);
}
__device__ __forceinline__ void cp16(uint32_t dst, const void* src) {
    asm volatile("cp.async.cg.shared.global [%0], [%1], 16;" :: "r"(dst), "l"(src));
}
__device__ __forceinline__ void ldsm4(uint32_t* r, uint32_t addr) {
    asm volatile("ldmatrix.sync.aligned.m8n8.x4.shared.b16 {%0,%1,%2,%3}, [%4];"
                 : "=r"(r[0]), "=r"(r[1]), "=r"(r[2]), "=r"(r[3]) : "r"(addr));
}
__device__ __forceinline__ void ldsm2(uint32_t* r, uint32_t addr) {
    asm volatile("ldmatrix.sync.aligned.m8n8.x2.shared.b16 {%0,%1}, [%2];"
                 : "=r"(r[0]), "=r"(r[1]) : "r"(addr));
}
__device__ __forceinline__ void ldsm2t(uint32_t* r, uint32_t addr) {
    asm volatile("ldmatrix.sync.aligned.m8n8.x2.trans.shared.b16 {%0,%1}, [%2];"
                 : "=r"(r[0]), "=r"(r[1]) : "r"(addr));
}
__device__ __forceinline__ void mma16816(float* c, const uint32_t* a, const uint32_t* b) {
    asm volatile(
        "mma.sync.aligned.m16n8k16.row.col.f32.f16.f16.f32 "
        "{%0,%1,%2,%3}, {%4,%5,%6,%7}, {%8,%9}, {%0,%1,%2,%3};"
        : "+f"(c[0]), "+f"(c[1]), "+f"(c[2]), "+f"(c[3])
        : "r"(a[0]), "r"(a[1]), "r"(a[2]), "r"(a[3]), "r"(b[0]), "r"(b[1]));
}

__device__ __forceinline__ uint32_t pack_h2(float a, float b) {
    __half2 h = __floats2half2_rn(a, b);
    return *(uint32_t*)&h;
}

// ---------------------------------------------------------------------------
// 128x128-tile single-pass fp16 HMMA GEMM. 128 threads = 4 warps (2m x 2n),
// warp tile 64x64. 3-stage cp.async ring (wait_group 1), grid = (nb, mt).
// ---------------------------------------------------------------------------
template<int NT, bool SCATTER, bool OUTF16>
__global__ __launch_bounds__(128) void gemm_mma(
    const __half* __restrict__ Af, const __half* __restrict__ Bf,
    const float* __restrict__ bias, float* __restrict__ out,
    __half* __restrict__ oh)
{
    extern __shared__ char smem[];
    const uint32_t sb = smem_u32(smem);
    const int tid = threadIdx.x, l = tid & 31, wid = tid >> 5;
    const int nb = blockIdx.x, mt = blockIdx.y;
    const int wm = wid >> 1, wn = wid & 1;

    float* bias_s = (float*)(smem + OFF_BIAS);
    bias_s[tid] = bias[nb * 128 + tid];

    // cp.async geometry: rows crow + i*16 (i<8), 16B chunk cc, for both A and B
    const int crow = tid >> 3;
    const int cc   = tid & 7;
    uint32_t smo[8];
    #pragma unroll
    for (int i = 0; i < 8; i++)
        smo[i] = sw128((crow + i * 16) * 128 + cc * 16);

    const __half* pA = Af + (size_t)(mt * 128 + crow) * CDIM + cc * 8;
    const __half* pB = Bf + (size_t)(nb * 128 + crow) * CDIM + cc * 8;

    // ldmatrix lane geometry
    const int sub = l >> 3;
    const int arl = wm * 64 + (sub & 1) * 8 + (l & 7);  // A row (+mi*16)
    const int acb = (sub >> 1) * 16;                    // A col byte (+k0b)
    const int brl = ((l >> 4) << 3) + (l & 7);          // B row within n16 (+njj*16)
    const int bcb = ((l >> 3) & 1) * 16;                // B col byte (+k0b)

    float acc[4][8][4];
    #pragma unroll
    for (int i = 0; i < 4; i++)
        #pragma unroll
        for (int j = 0; j < 8; j++)
            #pragma unroll
            for (int r = 0; r < 4; r++) acc[i][j][r] = 0.f;

    // prologue: prefetch chunks 0 and 1 into stages 0 and 1
    #pragma unroll
    for (int c = 0; c < 2; c++) {
        uint32_t buf = sb + c * STAGE_BYTES;
        int ko = c * 64;
        #pragma unroll
        for (int i = 0; i < 8; i++) {
            cp16(buf + smo[i],          pA + (size_t)(i * 16) * CDIM + ko);
            cp16(buf + SOFF_B + smo[i], pB + (size_t)(i * 16) * CDIM + ko);
        }
        asm volatile("cp.async.commit_group;");
    }

    #pragma unroll
    for (int k = 0; k < 4; k++) {
        if (k < 3) asm volatile("cp.async.wait_group 1;");
        else       asm volatile("cp.async.wait_group 0;");
        __syncthreads();   // also: buffer (k+2)%3 no longer being read

        if (k + 2 < 4) {
            uint32_t buf = sb + ((k + 2) % 3) * STAGE_BYTES;
            int ko = (k + 2) * 64;
            #pragma unroll
            for (int i = 0; i < 8; i++) {
                cp16(buf + smo[i],          pA + (size_t)(i * 16) * CDIM + ko);
                cp16(buf + SOFF_B + smo[i], pB + (size_t)(i * 16) * CDIM + ko);
            }
            asm volatile("cp.async.commit_group;");
        }

        const uint32_t cb = sb + (k % 3) * STAGE_BYTES;
        #pragma unroll
        for (int k16 = 0; k16 < 4; k16++) {
            const int k0b = k16 * 32;
            // B: 4x ldsm4, each covers n16 x k16 (2 MMA B-frags)
            uint32_t Bf2[8][2];
            #pragma unroll
            for (int njj = 0; njj < 4; njj++) {
                uint32_t r4[4];
                uint32_t r = (wn * 64 + njj * 16 + brl) * 128 + k0b + bcb;
                ldsm4(r4, cb + SOFF_B + sw128(r));
                Bf2[njj * 2][0]     = r4[0];
                Bf2[njj * 2][1]     = r4[1];
                Bf2[njj * 2 + 1][0] = r4[2];
                Bf2[njj * 2 + 1][1] = r4[3];
            }
            #pragma unroll
            for (int mi = 0; mi < 4; mi++) {
                uint32_t r = (arl + mi * 16) * 128 + k0b + acb;
                uint32_t Afr[4];
                ldsm4(Afr, cb + sw128(r));
                #pragma unroll
                for (int ni = 0; ni < 8; ni++)
                    mma16816(acc[mi][ni], Afr, Bf2[ni]);
            }
        }
    }
    __syncthreads();

    // epilogue via smem stage (128 x 132 floats = 67.6KB, fits in ring area)
    float* stage = (float*)smem;
    #pragma unroll
    for (int mi = 0; mi < 4; mi++)
        #pragma unroll
        for (int ni = 0; ni < 8; ni++) {
            int r   = wm * 64 + mi * 16 + (l >> 2);
            int col = wn * 64 + ni * 8 + (l & 3) * 2;
            *(float2*)&stage[r * 132 + col]       = make_float2(acc[mi][ni][0], acc[mi][ni][1]);
            *(float2*)&stage[(r + 8) * 132 + col] = make_float2(acc[mi][ni][2], acc[mi][ni][3]);
        }
    __syncthreads();

    #pragma unroll
    for (int it = 0; it < 32; it++) {
        int idx = it * 128 + tid;
        int r  = idx >> 5, c4 = (idx & 31) * 4;
        float4 o;
        o.x = stage[r * 132 + c4 + 0] + bias_s[c4 + 0];
        o.y = stage[r * 132 + c4 + 1] + bias_s[c4 + 1];
        o.z = stage[r * 132 + c4 + 2] + bias_s[c4 + 2];
        o.w = stage[r * 132 + c4 + 3] + bias_s[c4 + 3];
        int lrow = mt * 128 + r;
        int orow = SCATTER ? global_row(lrow >> 6, lrow & 63) : lrow;
        size_t off = (size_t)orow * NT + nb * 128 + c4;
        if (OUTF16) {
            *(uint2*)(oh + off) = make_uint2(pack_h2(o.x, o.y), pack_h2(o.z, o.w));
        } else {
            *(float4*)(out + off) = o;
        }
    }
}

// ---------------------------------------------------------------------------
// Pre-pass: gather x into window order, convert to fp16
// ---------------------------------------------------------------------------
__global__ __launch_bounds__(256) void convert_x(const float* __restrict__ x) {
    const int win = blockIdx.x;
    const int tid = threadIdx.x;
    #pragma unroll
    for (int i = 0; i < 16; i++) {
        int idx4 = i * 256 + tid;
        int row  = idx4 >> 6;
        int c4   = idx4 & 63;
        int grow = global_row(win, row);
        float4 v = *(const float4*)(x + (size_t)grow * CDIM + c4 * 4);
        size_t o = ((size_t)win * WS2 + row) * CDIM + c4 * 4;
        *(uint2*)(g_x_f16 + o) = make_uint2(pack_h2(v.x, v.y), pack_h2(v.z, v.w));
    }
}

__global__ void convert_w(const float* __restrict__ wq, const float* __restrict__ wo) {
    int n = blockIdx.x, k = threadIdx.x;
    if (n < QKV_N) {
        g_wq[n * CDIM + k] = __float2half_rn(wq[k * QKV_N + n]);
    } else {
        int n2 = n - QKV_N;
        g_wo[n2 * CDIM + k] = __float2half_rn(wo[k * CDIM + n2]);
    }
}

// ---------------------------------------------------------------------------
// Build bias+mask table: [head][class][64q][64k]
// ---------------------------------------------------------------------------
__global__ void build_bias(const float* __restrict__ pos) {
    int h = blockIdx.x >> 2, cls = blockIdx.x & 3;
    int wy = (cls & 2) ? 7 : 0, wx = (cls & 1) ? 7 : 0;
    for (int it = 0; it < 16; it++) {
        int idx = it * 256 + threadIdx.x;
        int q = idx >> 6, k = idx & 63;
        int qy = q >> 3, qx = q & 7, ky = k >> 3, kx = k & 7;
        int gy = wy * 8 + qy, gx = wx * 8 + qx;
        int hy = wy * 8 + ky, hx = wx * 8 + kx;
        int rq = (gy < 56 ? 0 : (gy < 60 ? 1 : 2)) * 3 + (gx < 56 ? 0 : (gx < 60 ? 1 : 2));
        int rk = (hy < 56 ? 0 : (hy < 60 ? 1 : 2)) * 3 + (hx < 56 ? 0 : (hx < 60 ? 1 : 2));
        float v = (rq == rk) ? pos[h * 225 + (qy - ky + 7) * 15 + (qx - kx + 7)] : -1e30f;
        g_bias[(size_t)(h * 4 + cls) * 4096 + idx] = v;
    }
}

// ---------------------------------------------------------------------------
// fp16 HMMA attention. Block = (2 heads, window), 4 warps; warp = 32q x 64k.
// ---------------------------------------------------------------------------
__global__ __launch_bounds__(128) void attn_mma(const __half* __restrict__ qkv)
{
    extern __shared__ char smem[];
    const uint32_t sb = smem_u32(smem);
    const int tid = threadIdx.x, l = tid & 31, wid = tid >> 5;
    const int hg  = blockIdx.x;
    const int win = blockIdx.y;
    const int wi  = win & 63, wy = wi >> 3, wx = wi & 7;
    const int cls = ((wy == 7) ? 2 : 0) | ((wx == 7) ? 1 : 0);

    #pragma unroll
    for (int i = 0; i < 12; i++) {
        int idx  = i * 128 + tid;
        int mat  = idx >> 9;
        int rem  = idx & 511;
        int row  = rem >> 3;
        int ch   = rem & 7;
        int hsel = ch >> 2;
        int c16  = ch & 3;
        uint32_t dst = sb + mat * 8192 + sw128(row * 128 + hsel * 64 + c16 * 16);
        const __half* src = qkv + (size_t)(win * 64 + row) * QKV_N
                          + (hg * 2 + hsel) * 32 + mat * 256 + c16 * 8;
        cp16(dst, src);
    }
    asm volatile("cp.async.commit_group;");
    asm volatile("cp.async.wait_group 0;");
    __syncthreads();

    const int hl = wid >> 1;
    const int w  = wid & 1;
    const uint32_t QB = sb;
    const uint32_t KB = sb + 8192;
    const uint32_t VB = sb + 16384;
    const float* T = g_bias + (size_t)((hg * 2 + hl) * 4 + cls) * 4096;

    const int sub = l >> 3;
    const int arl = (sub & 1) * 8 + (l & 7);
    const int acb = (sub >> 1) * 16;
    const int lb  = l & 15;
    const int brl = lb & 7;
    const int bcb = (lb >> 3) * 16;

    float sc[2][8][4];
    #pragma unroll
    for (int mi = 0; mi < 2; mi++)
        #pragma unroll
        for (int ni = 0; ni < 8; ni++)
            #pragma unroll
            for (int r = 0; r < 4; r++) sc[mi][ni][r] = 0.f;

    #pragma unroll
    for (int k16 = 0; k16 < 2; k16++) {
        uint32_t A[2][4];
        #pragma unroll
        for (int mi = 0; mi < 2; mi++) {
            uint32_t r = (w * 32 + mi * 16 + arl) * 128 + hl * 64 + k16 * 32 + acb;
            ldsm4(A[mi], QB + sw128(r));
        }
        #pragma unroll
        for (int ni = 0; ni < 8; ni++) {
            uint32_t B[2];
            uint32_t r = (ni * 8 + brl) * 128 + hl * 64 + k16 * 32 + bcb;
            ldsm2(B, KB + sw128(r));
            #pragma unroll
            for (int mi = 0; mi < 2; mi++)
                mma16816(sc[mi][ni], A[mi], B);
        }
    }

    float rinv[2][2];
    #pragma unroll
    for (int mi = 0; mi < 2; mi++)
        #pragma unroll
        for (int rr = 0; rr < 2; rr++) {
            int r = w * 32 + mi * 16 + rr * 8 + (l >> 2);
            const float* Tr = T + r * 64 + (l & 3) * 2;
            float m = -1e30f;
            #pragma unroll
            for (int ni = 0; ni < 8; ni++) {
                float2 b2 = *(const float2*)(Tr + ni * 8);
                float v0 = sc[mi][ni][rr * 2]     * SCALE + b2.x;
                float v1 = sc[mi][ni][rr * 2 + 1] * SCALE + b2.y;
                sc[mi][ni][rr * 2]     = v0;
                sc[mi][ni][rr * 2 + 1] = v1;
                m = fmaxf(m, fmaxf(v0, v1));
            }
            m = fmaxf(m, __shfl_xor_sync(0xffffffffu, m, 1));
            m = fmaxf(m, __shfl_xor_sync(0xffffffffu, m, 2));
            float s = 0.f;
            #pragma unroll
            for (int ni = 0; ni < 8; ni++)
                #pragma unroll
                for (int j = 0; j < 2; j++) {
                    float e = __expf(sc[mi][ni][rr * 2 + j] - m);
                    sc[mi][ni][rr * 2 + j] = e;
                    s += e;
                }
            s += __shfl_xor_sync(0xffffffffu, s, 1);
            s += __shfl_xor_sync(0xffffffffu, s, 2);
            rinv[mi][rr] = 1.0f / s;
        }

    __syncthreads();

    const uint32_t PB = sb + (hl * 2 + w) * 4096;
    #pragma unroll
    for (int mi = 0; mi < 2; mi++)
        #pragma unroll
        for (int rr = 0; rr < 2; rr++) {
            int lr = mi * 16 + rr * 8 + (l >> 2);
            #pragma unroll
            for (int ni = 0; ni < 8; ni++) {
                uint32_t off = sw128(lr * 128 + ni * 16 + (l & 3) * 4);
                *(uint32_t*)(smem + (PB - sb) + off) =
                    pack_h2(sc[mi][ni][rr * 2], sc[mi][ni][rr * 2 + 1]);
            }
        }
    __syncwarp();

    float o[2][4][4];
    #pragma unroll
    for (int mi = 0; mi < 2; mi++)
        #pragma unroll
        for (int nj = 0; nj < 4; nj++)
            #pragma unroll
            for (int r = 0; r < 4; r++) o[mi][nj][r] = 0.f;

    #pragma unroll
    for (int k16 = 0; k16 < 4; k16++) {
        uint32_t P[2][4];
        #pragma unroll
        for (int mi = 0; mi < 2; mi++) {
            uint32_t r = (mi * 16 + arl) * 128 + k16 * 32 + acb;
            ldsm4(P[mi], PB + sw128(r));
        }
        #pragma unroll
        for (int nj = 0; nj < 4; nj++) {
            uint32_t V[2];
            uint32_t r = (k16 * 16 + lb) * 128 + hl * 64 + nj * 16;
            ldsm2t(V, VB + sw128(r));
            #pragma unroll
            for (int mi = 0; mi < 2; mi++)
                mma16816(o[mi][nj], P[mi], V);
        }
    }

    const int head = hg * 2 + hl;
    #pragma unroll
    for (int mi = 0; mi < 2; mi++)
        #pragma unroll
        for (int rr = 0; rr < 2; rr++) {
            int r = w * 32 + mi * 16 + rr * 8 + (l >> 2);
            float inv = rinv[mi][rr];
            size_t rowoff = (size_t)(win * 64 + r) * CDIM + head * 32;
            #pragma unroll
            for (int nj = 0; nj < 4; nj++) {
                int c = nj * 8 + (l & 3) * 2;
                *(uint32_t*)(g_att_f16 + rowoff + c) =
                    pack_h2(o[mi][nj][rr * 2] * inv, o[mi][nj][rr * 2 + 1] * inv);
            }
        }
}

// ---------------------------------------------------------------------------
extern "C" void kernel_launch(void* const* d_in, const int* in_sizes, int n_in,
                              void* d_out, int out_size) {
    const float* x     = (const float*)d_in[0];
    const float* w_qkv = (const float*)d_in[1];
    const float* b_qkv = (const float*)d_in[2];
    const float* w_out = (const float*)d_in[3];
    const float* b_out = (const float*)d_in[4];
    const float* pos   = (const float*)d_in[5];
    float* out = (float*)d_out;

    __half *qkv, *xf, *af, *wq, *wo;
    cudaGetSymbolAddress((void**)&qkv, g_qkv_f16);
    cudaGetSymbolAddress((void**)&xf,  g_x_f16);
    cudaGetSymbolAddress((void**)&af,  g_att_f16);
    cudaGetSymbolAddress((void**)&wq,  g_wq);
    cudaGetSymbolAddress((void**)&wo,  g_wo);

    cudaFuncSetAttribute(gemm_mma<QKV_N, false, true>,
                         cudaFuncAttributeMaxDynamicSharedMemorySize, SMEM_GEMM);
    cudaFuncSetAttribute(gemm_mma<CDIM, true, false>,
                         cudaFuncAttributeMaxDynamicSharedMemorySize, SMEM_GEMM);
    cudaFuncSetAttribute(attn_mma,
                         cudaFuncAttributeMaxDynamicSharedMemorySize, SMEM_ATT);

    convert_w<<<1024, 256>>>(w_qkv, w_out);
    build_bias<<<32, 256>>>(pos);
    convert_x<<<NWIN, 256>>>(x);
    gemm_mma<QKV_N, false, true><<<dim3(6, 1024), 128, SMEM_GEMM>>>(
        xf, wq, b_qkv, nullptr, qkv);
    attn_mma<<<dim3(4, NWIN), 128, SMEM_ATT>>>(qkv);
    gemm_mma<CDIM, true, false><<<dim3(2, 1024), 128, SMEM_GEMM>>>(
        af, wo, b_out, out, nullptr);
}